// round 1
// baseline (speedup 1.0000x reference)
#include <cuda_runtime.h>
#include <math.h>

// ---------------- problem constants ----------------
#define L_TOK 32768          // B*H*W tokens
#define C_DIM 256
#define HID_DIM 1024
#define NW 256               // number of windows (16 x 16)
#define NH 8                 // heads
#define T_WIN 128            // tokens per window
#define HD 32                // head dim
#define W_IMG 512
#define EPS 1e-5f
#define SCALE 0.17677669529663687f   // 32^-0.5

// ---------------- scratch (static device memory; no allocations) ----------------
// layout: xn | q | k | v | o | x1 | xn2 | hid
static const size_t SZ_LC = (size_t)L_TOK * C_DIM;            // 8,388,608 floats
__device__ float g_scratch[8 * 8388608ull + (size_t)L_TOK * HID_DIM];

// ---------------- LayerNorm ----------------
__global__ void ln_kernel(const float* __restrict__ x,
                          const float* __restrict__ g,
                          const float* __restrict__ b,
                          float* __restrict__ y)
{
    const int row = blockIdx.x;
    const int tid = threadIdx.x;                 // 256 threads, one per channel
    const float v = x[(long)row * C_DIM + tid];

    float s = v, sq = v * v;
    #pragma unroll
    for (int o = 16; o > 0; o >>= 1) {
        s  += __shfl_xor_sync(0xffffffffu, s, o);
        sq += __shfl_xor_sync(0xffffffffu, sq, o);
    }
    __shared__ float ss[8], ssq[8];
    if ((tid & 31) == 0) { ss[tid >> 5] = s; ssq[tid >> 5] = sq; }
    __syncthreads();
    float S = 0.f, SQ = 0.f;
    #pragma unroll
    for (int i = 0; i < 8; i++) { S += ss[i]; SQ += ssq[i]; }
    const float mean = S * (1.f / 256.f);
    const float var  = SQ * (1.f / 256.f) - mean * mean;
    const float inv  = rsqrtf(var + EPS);
    y[(long)row * C_DIM + tid] = (v - mean) * inv * g[tid] + b[tid];
}

// ---------------- SGEMM: C[M,N] = A[M,K] @ B[K,N] (+bias, +epilogue) ----------------
// OP 0: (acc + bias) * scale
// OP 1: acc + bias + R[m,n]        (residual add)
// OP 2: gelu(acc + bias)           (exact erf gelu)
template<int OP>
__global__ void gemm_kernel(const float* __restrict__ A, const float* __restrict__ B,
                            const float* __restrict__ bias, const float* __restrict__ R,
                            float* __restrict__ C, int M, int N, int K, float scale)
{
    __shared__ float As[16][64];
    __shared__ float Bs[16][64];

    const int tid = threadIdx.x;                 // 256 threads
    const int m0 = blockIdx.y * 64;
    const int n0 = blockIdx.x * 64;
    const int tx = tid & 15;                     // 16 cols of 4
    const int ty = tid >> 4;                     // 16 rows of 4

    const int aRow = tid >> 2;                   // 0..63
    const int aCol = (tid & 3) * 4;              // 0..12
    const int bRow = tid >> 4;                   // 0..15
    const int bCol = (tid & 15) * 4;             // 0..60

    const float* Aptr = A + (long)(m0 + aRow) * K + aCol;
    const float* Bptr = B + (long)bRow * N + n0 + bCol;

    float acc[4][4] = {};

    for (int k0 = 0; k0 < K; k0 += 16) {
        float4 a4 = *reinterpret_cast<const float4*>(Aptr + k0);
        float4 b4 = *reinterpret_cast<const float4*>(Bptr + (long)k0 * N);
        As[aCol + 0][aRow] = a4.x;
        As[aCol + 1][aRow] = a4.y;
        As[aCol + 2][aRow] = a4.z;
        As[aCol + 3][aRow] = a4.w;
        *reinterpret_cast<float4*>(&Bs[bRow][bCol]) = b4;
        __syncthreads();

        #pragma unroll
        for (int k = 0; k < 16; k++) {
            const float4 av = *reinterpret_cast<const float4*>(&As[k][ty * 4]);
            const float4 bv = *reinterpret_cast<const float4*>(&Bs[k][tx * 4]);
            const float a[4] = {av.x, av.y, av.z, av.w};
            const float b[4] = {bv.x, bv.y, bv.z, bv.w};
            #pragma unroll
            for (int i = 0; i < 4; i++)
                #pragma unroll
                for (int j = 0; j < 4; j++)
                    acc[i][j] = fmaf(a[i], b[j], acc[i][j]);
        }
        __syncthreads();
    }

    float bn[4];
    #pragma unroll
    for (int j = 0; j < 4; j++) bn[j] = bias[n0 + tx * 4 + j];

    #pragma unroll
    for (int i = 0; i < 4; i++) {
        const int row = m0 + ty * 4 + i;
        #pragma unroll
        for (int j = 0; j < 4; j++) {
            const int col = n0 + tx * 4 + j;
            float v = acc[i][j] + bn[j];
            if (OP == 0) v *= scale;
            if (OP == 1) v += R[(long)row * N + col];
            if (OP == 2) v = 0.5f * v * (1.f + erff(v * 0.70710678118654752f));
            C[(long)row * N + col] = v;
        }
    }
}

// ---------------- fused windowed attention ----------------
struct AttnSmem {
    float S[T_WIN][T_WIN + 1];   // padded scores: kills stride-512B bank conflict
    float K[T_WIN][HD];
    float V[T_WIN][HD];
    float px[T_WIN];
    float py[T_WIN];
    int   l[T_WIN];
};

__global__ void attn_kernel(const float* __restrict__ Q, const float* __restrict__ K,
                            const float* __restrict__ V, const float* __restrict__ pos,
                            const float* __restrict__ pw1, const float* __restrict__ pb1,
                            const float* __restrict__ bn_g, const float* __restrict__ bn_b,
                            const float* __restrict__ bn_m, const float* __restrict__ bn_v,
                            const float* __restrict__ pw2, const float* __restrict__ pb2,
                            float* __restrict__ O)
{
    extern __shared__ char smem_raw[];
    AttnSmem& sm = *reinterpret_cast<AttnSmem*>(smem_raw);

    const int h = blockIdx.x;     // head
    const int n = blockIdx.y;     // window
    const int t = threadIdx.x;    // query row (128 threads)
    const int wr = n >> 4, wc = n & 15;
    const int l_t = (wr * 4 + (t >> 5)) * W_IMG + wc * 32 + (t & 31);
    const int cbase = h * HD;

    sm.l[t]  = l_t;
    sm.px[t] = pos[(long)l_t * 2 + 0];
    sm.py[t] = pos[(long)l_t * 2 + 1];
    __syncthreads();

    // cooperative K/V tile load (128B coalesced chunks)
    for (int i = t; i < T_WIN * HD; i += T_WIN) {
        const int u = i >> 5, d = i & 31;
        const long base = (long)sm.l[u] * C_DIM + cbase + d;
        sm.K[u][d] = K[base];
        sm.V[u][d] = V[base];
    }

    // fused conv1+BN coefficients and pw2 row for this head (registers)
    float cA[16], cB[16], cC[16], cW[16];
    #pragma unroll
    for (int i = 0; i < 16; i++) {
        const float s = bn_g[i] * rsqrtf(bn_v[i] + EPS);
        cA[i] = pw1[2 * i + 0] * s;
        cB[i] = pw1[2 * i + 1] * s;
        cC[i] = (pb1[i] - bn_m[i]) * s + bn_b[i];
        cW[i] = pw2[h * 16 + i];
    }
    const float pb2h = pb2[h];
    __syncthreads();

    // Phase A: positional bias -> S. Thread t owns column u = t.
    const float pxu = sm.px[t], pyu = sm.py[t];
    for (int tt = 0; tt < T_WIN; tt++) {
        const float dx = sm.px[tt] - pxu;
        const float dy = sm.py[tt] - pyu;
        float bsum = pb2h;
        #pragma unroll
        for (int i = 0; i < 16; i++) {
            float f = fmaf(cA[i], dx, fmaf(cB[i], dy, cC[i]));
            bsum = fmaf(cW[i], fmaxf(f, 0.f), bsum);
        }
        sm.S[tt][t] = bsum;
    }
    __syncthreads();

    // Phase B: S += q . k^T (q pre-scaled), row max
    float q[HD];
    #pragma unroll
    for (int d = 0; d < HD; d++) q[d] = Q[(long)l_t * C_DIM + cbase + d];

    float m = -1e30f;
    for (int u = 0; u < T_WIN; u++) {
        float s = sm.S[t][u];
        #pragma unroll
        for (int d = 0; d < HD; d++) s = fmaf(q[d], sm.K[u][d], s);
        sm.S[t][u] = s;
        m = fmaxf(m, s);
    }

    // softmax
    float rs = 0.f;
    for (int u = 0; u < T_WIN; u++) {
        const float p = __expf(sm.S[t][u] - m);
        sm.S[t][u] = p;
        rs += p;
    }
    const float inv = 1.f / rs;

    // Phase C: O = P @ V
    float acc[HD];
    #pragma unroll
    for (int d = 0; d < HD; d++) acc[d] = 0.f;
    for (int u = 0; u < T_WIN; u++) {
        const float p = sm.S[t][u];
        #pragma unroll
        for (int d = 0; d < HD; d++) acc[d] = fmaf(p, sm.V[u][d], acc[d]);
    }
    #pragma unroll
    for (int d = 0; d < HD; d++)
        O[(long)l_t * C_DIM + cbase + d] = acc[d] * inv;
}

// ---------------- launch ----------------
extern "C" void kernel_launch(void* const* d_in, const int* in_sizes, int n_in,
                              void* d_out, int out_size)
{
    const float* x      = (const float*)d_in[0];
    const float* pos    = (const float*)d_in[1];
    const float* n1g    = (const float*)d_in[2];
    const float* n1b    = (const float*)d_in[3];
    const float* wq     = (const float*)d_in[4];
    const float* bq     = (const float*)d_in[5];
    const float* wk     = (const float*)d_in[6];
    const float* bk     = (const float*)d_in[7];
    const float* wv     = (const float*)d_in[8];
    const float* bv     = (const float*)d_in[9];
    const float* wo     = (const float*)d_in[10];
    const float* bo     = (const float*)d_in[11];
    const float* n2g    = (const float*)d_in[12];
    const float* n2b    = (const float*)d_in[13];
    const float* wfc1   = (const float*)d_in[14];
    const float* bfc1   = (const float*)d_in[15];
    const float* wfc2   = (const float*)d_in[16];
    const float* bfc2   = (const float*)d_in[17];
    const float* pw1    = (const float*)d_in[18];
    const float* pb1    = (const float*)d_in[19];
    const float* bn_g   = (const float*)d_in[20];
    const float* bn_b   = (const float*)d_in[21];
    const float* bn_m   = (const float*)d_in[22];
    const float* bn_v   = (const float*)d_in[23];
    const float* pw2    = (const float*)d_in[24];
    const float* pb2    = (const float*)d_in[25];
    float* out = (float*)d_out;

    float* base = nullptr;
    cudaGetSymbolAddress((void**)&base, g_scratch);
    float* xn  = base + 0 * SZ_LC;
    float* q   = base + 1 * SZ_LC;
    float* k   = base + 2 * SZ_LC;
    float* v   = base + 3 * SZ_LC;
    float* o   = base + 4 * SZ_LC;
    float* x1  = base + 5 * SZ_LC;
    float* xn2 = base + 6 * SZ_LC;
    float* hid = base + 7 * SZ_LC;

    cudaFuncSetAttribute(attn_kernel, cudaFuncAttributeMaxDynamicSharedMemorySize,
                         (int)sizeof(AttnSmem));

    // 1. xn = LN1(x)
    ln_kernel<<<L_TOK, 256>>>(x, n1g, n1b, xn);

    // 2-4. Q (scaled), K, V projections
    gemm_kernel<0><<<dim3(C_DIM / 64, L_TOK / 64), 256>>>(xn, wq, bq, nullptr, q,
                                                          L_TOK, C_DIM, C_DIM, SCALE);
    gemm_kernel<0><<<dim3(C_DIM / 64, L_TOK / 64), 256>>>(xn, wk, bk, nullptr, k,
                                                          L_TOK, C_DIM, C_DIM, 1.f);
    gemm_kernel<0><<<dim3(C_DIM / 64, L_TOK / 64), 256>>>(xn, wv, bv, nullptr, v,
                                                          L_TOK, C_DIM, C_DIM, 1.f);

    // 5. windowed attention with fused positional-bias MLP
    attn_kernel<<<dim3(NH, NW), T_WIN, sizeof(AttnSmem)>>>(
        q, k, v, pos, pw1, pb1, bn_g, bn_b, bn_m, bn_v, pw2, pb2, o);

    // 6. x1 = x + o @ wo + bo
    gemm_kernel<1><<<dim3(C_DIM / 64, L_TOK / 64), 256>>>(o, wo, bo, x, x1,
                                                          L_TOK, C_DIM, C_DIM, 1.f);

    // 7. xn2 = LN2(x1)
    ln_kernel<<<L_TOK, 256>>>(x1, n2g, n2b, xn2);

    // 8. hid = gelu(xn2 @ wfc1 + bfc1)
    gemm_kernel<2><<<dim3(HID_DIM / 64, L_TOK / 64), 256>>>(xn2, wfc1, bfc1, nullptr, hid,
                                                            L_TOK, HID_DIM, C_DIM, 1.f);

    // 9. out = x1 + hid @ wfc2 + bfc2
    gemm_kernel<1><<<dim3(C_DIM / 64, L_TOK / 64), 256>>>(hid, wfc2, bfc2, x1, out,
                                                          L_TOK, C_DIM, HID_DIM, 1.f);
}

// round 2
// speedup vs baseline: 2.5374x; 2.5374x over previous
#include <cuda_runtime.h>
#include <cuda_bf16.h>
#include <math.h>

using bf16 = __nv_bfloat16;

// ---------------- problem constants ----------------
#define L_TOK 32768
#define C_DIM 256
#define HID_DIM 1024
#define NW 256
#define NH 8
#define T_WIN 128
#define HD 32
#define W_IMG 512
#define EPS 1e-5f
#define SCALE 0.17677669529663687f

// ---------------- scratch ----------------
static const size_t SZ_LC = (size_t)L_TOK * C_DIM;
__device__ float g_scratch[8 * 8388608ull + (size_t)L_TOK * HID_DIM];
__device__ bf16  g_wbf[786432];   // wq|wk|wv|wo (65536 each) | wfc1 (262144) | wfc2 (262144)

// ---------------- fp32 -> bf16 convert ----------------
__global__ void f2bf_kernel(const float* __restrict__ in, bf16* __restrict__ out, int n)
{
    for (int i = blockIdx.x * blockDim.x + threadIdx.x; i < n; i += gridDim.x * blockDim.x)
        out[i] = __float2bfloat16(in[i]);
}

// ---------------- LayerNorm (bf16 output) ----------------
__global__ void ln_kernel(const float* __restrict__ x,
                          const float* __restrict__ g,
                          const float* __restrict__ b,
                          bf16* __restrict__ y)
{
    const int row = blockIdx.x;
    const int tid = threadIdx.x;
    const float v = x[(long)row * C_DIM + tid];

    float s = v, sq = v * v;
    #pragma unroll
    for (int o = 16; o > 0; o >>= 1) {
        s  += __shfl_xor_sync(0xffffffffu, s, o);
        sq += __shfl_xor_sync(0xffffffffu, sq, o);
    }
    __shared__ float ss[8], ssq[8];
    if ((tid & 31) == 0) { ss[tid >> 5] = s; ssq[tid >> 5] = sq; }
    __syncthreads();
    float S = 0.f, SQ = 0.f;
    #pragma unroll
    for (int i = 0; i < 8; i++) { S += ss[i]; SQ += ssq[i]; }
    const float mean = S * (1.f / 256.f);
    const float var  = SQ * (1.f / 256.f) - mean * mean;
    const float inv  = rsqrtf(var + EPS);
    y[(long)row * C_DIM + tid] = __float2bfloat16((v - mean) * inv * g[tid] + b[tid]);
}

// ---------------- tensor-core GEMM ----------------
// C[M,N] = A[M,K](bf16) @ B[K,N](bf16) + bias, epilogue OP:
//   OP 0: * scale (fp32 out)
//   OP 1: + R     (fp32 out, residual)
//   OP 2: gelu    (bf16 out)
__device__ __forceinline__ void cp16(unsigned saddr, const void* g)
{
    asm volatile("cp.async.cg.shared.global [%0], [%1], 16;" :: "r"(saddr), "l"(g));
}
__device__ __forceinline__ void ldsm4(unsigned* r, unsigned addr)
{
    asm volatile("ldmatrix.sync.aligned.m8n8.x4.shared.b16 {%0,%1,%2,%3}, [%4];"
                 : "=r"(r[0]), "=r"(r[1]), "=r"(r[2]), "=r"(r[3]) : "r"(addr));
}
__device__ __forceinline__ void ldsm4t(unsigned* r, unsigned addr)
{
    asm volatile("ldmatrix.sync.aligned.m8n8.x4.trans.shared.b16 {%0,%1,%2,%3}, [%4];"
                 : "=r"(r[0]), "=r"(r[1]), "=r"(r[2]), "=r"(r[3]) : "r"(addr));
}
__device__ __forceinline__ void mma16816(float* d, const unsigned* a, const unsigned* b)
{
    asm volatile("mma.sync.aligned.m16n8k16.row.col.f32.bf16.bf16.f32 "
                 "{%0,%1,%2,%3}, {%4,%5,%6,%7}, {%8,%9}, {%0,%1,%2,%3};"
                 : "+f"(d[0]), "+f"(d[1]), "+f"(d[2]), "+f"(d[3])
                 : "r"(a[0]), "r"(a[1]), "r"(a[2]), "r"(a[3]), "r"(b[0]), "r"(b[1]));
}

#define A_STRIDE 40    // bf16 units per A smem row (80B, conflict-free ldmatrix)
#define B_STRIDE 136   // bf16 units per B smem row (272B, conflict-free ldmatrix)

template<int OP, bool BF_OUT>
__global__ __launch_bounds__(256, 2)
void mma_gemm(const bf16* __restrict__ A, const bf16* __restrict__ B,
              const float* __restrict__ bias, const float* __restrict__ R,
              void* __restrict__ Cout, int M, int N, int K, float scale)
{
    __shared__ bf16 As[2][128 * A_STRIDE];
    __shared__ bf16 Bs[2][32 * B_STRIDE];

    const int tid  = threadIdx.x;
    const int lane = tid & 31;
    const int wid  = tid >> 5;
    const int wm   = wid >> 1;          // 0..3
    const int wn   = wid & 1;           // 0..1
    const int m0   = blockIdx.y * 128;
    const int n0   = blockIdx.x * 128;

    unsigned asb[2] = { (unsigned)__cvta_generic_to_shared(&As[0][0]),
                        (unsigned)__cvta_generic_to_shared(&As[1][0]) };
    unsigned bsb[2] = { (unsigned)__cvta_generic_to_shared(&Bs[0][0]),
                        (unsigned)__cvta_generic_to_shared(&Bs[1][0]) };

    // global->smem chunk mapping (16B chunks, 2 per thread per tile)
    const int arow0 = tid >> 2,        ach0 = (tid & 3);
    const int arow1 = (tid + 256) >> 2, ach1 = ((tid + 256) & 3);
    const int brow0 = tid >> 4,        bch0 = (tid & 15);
    const int brow1 = (tid + 256) >> 4, bch1 = ((tid + 256) & 15);

    auto issue = [&](int kt, int buf) {
        const int kb = kt * 32;
        cp16(asb[buf] + (arow0 * A_STRIDE + ach0 * 8) * 2,
             A + (long)(m0 + arow0) * K + kb + ach0 * 8);
        cp16(asb[buf] + (arow1 * A_STRIDE + ach1 * 8) * 2,
             A + (long)(m0 + arow1) * K + kb + ach1 * 8);
        cp16(bsb[buf] + (brow0 * B_STRIDE + bch0 * 8) * 2,
             B + (long)(kb + brow0) * N + n0 + bch0 * 8);
        cp16(bsb[buf] + (brow1 * B_STRIDE + bch1 * 8) * 2,
             B + (long)(kb + brow1) * N + n0 + bch1 * 8);
        asm volatile("cp.async.commit_group;");
    };

    // ldmatrix per-lane address components
    const int mat = lane >> 3, r8 = lane & 7;
    const int a_row = wm * 32 + (mat & 1) * 8 + r8;   // + mt*16
    const int a_col = (mat >> 1) * 8;                 // + ks*16
    const int b_kr  = (mat & 1) * 8 + r8;             // + ks*16
    const int b_nc  = wn * 64 + (mat >> 1) * 8;       // + nt*16

    float acc[2][8][4];
    #pragma unroll
    for (int i = 0; i < 2; i++)
        #pragma unroll
        for (int j = 0; j < 8; j++)
            #pragma unroll
            for (int k = 0; k < 4; k++) acc[i][j][k] = 0.f;

    const int KT = K >> 5;
    issue(0, 0);

    for (int kt = 0; kt < KT; kt++) {
        if (kt + 1 < KT) {
            issue(kt + 1, (kt + 1) & 1);
            asm volatile("cp.async.wait_group %0;" :: "n"(1));
        } else {
            asm volatile("cp.async.wait_group %0;" :: "n"(0));
        }
        __syncthreads();

        const int buf = kt & 1;
        #pragma unroll
        for (int ks = 0; ks < 2; ks++) {
            unsigned a[2][4], b[4][4];
            #pragma unroll
            for (int mt = 0; mt < 2; mt++)
                ldsm4(a[mt], asb[buf] + ((a_row + mt * 16) * A_STRIDE + a_col + ks * 16) * 2);
            #pragma unroll
            for (int nt = 0; nt < 4; nt++)
                ldsm4t(b[nt], bsb[buf] + ((b_kr + ks * 16) * B_STRIDE + b_nc + nt * 16) * 2);
            #pragma unroll
            for (int mt = 0; mt < 2; mt++)
                #pragma unroll
                for (int n8 = 0; n8 < 8; n8++)
                    mma16816(acc[mt][n8], a[mt], &b[n8 >> 1][(n8 & 1) * 2]);
        }
        __syncthreads();
    }

    // epilogue
    const int gr = lane >> 2, tig = lane & 3;
    #pragma unroll
    for (int mt = 0; mt < 2; mt++) {
        #pragma unroll
        for (int n8 = 0; n8 < 8; n8++) {
            const int col = n0 + wn * 64 + n8 * 8 + tig * 2;
            const float b0 = bias[col], b1 = bias[col + 1];
            #pragma unroll
            for (int half = 0; half < 2; half++) {
                const int row = m0 + wm * 32 + mt * 16 + gr + half * 8;
                float v0 = acc[mt][n8][half * 2 + 0] + b0;
                float v1 = acc[mt][n8][half * 2 + 1] + b1;
                if (OP == 0) { v0 *= scale; v1 *= scale; }
                if (OP == 1) {
                    const float2 rr = *reinterpret_cast<const float2*>(R + (long)row * N + col);
                    v0 += rr.x; v1 += rr.y;
                }
                if (OP == 2) {
                    v0 = 0.5f * v0 * (1.f + erff(v0 * 0.70710678118654752f));
                    v1 = 0.5f * v1 * (1.f + erff(v1 * 0.70710678118654752f));
                }
                if (BF_OUT) {
                    bf16* C = (bf16*)Cout;
                    __nv_bfloat162 p = __floats2bfloat162_rn(v0, v1);
                    *reinterpret_cast<__nv_bfloat162*>(C + (long)row * N + col) = p;
                } else {
                    float* C = (float*)Cout;
                    float2 p = make_float2(v0, v1);
                    *reinterpret_cast<float2*>(C + (long)row * N + col) = p;
                }
            }
        }
    }
}

// ---------------- fused windowed attention (fp32, bf16 output) ----------------
struct AttnSmem {
    float S[T_WIN][T_WIN + 1];
    float K[T_WIN][HD];
    float V[T_WIN][HD];
    float px[T_WIN];
    float py[T_WIN];
    int   l[T_WIN];
};

__global__ void attn_kernel(const float* __restrict__ Q, const float* __restrict__ K,
                            const float* __restrict__ V, const float* __restrict__ pos,
                            const float* __restrict__ pw1, const float* __restrict__ pb1,
                            const float* __restrict__ bn_g, const float* __restrict__ bn_b,
                            const float* __restrict__ bn_m, const float* __restrict__ bn_v,
                            const float* __restrict__ pw2, const float* __restrict__ pb2,
                            bf16* __restrict__ O)
{
    extern __shared__ char smem_raw[];
    AttnSmem& sm = *reinterpret_cast<AttnSmem*>(smem_raw);

    const int h = blockIdx.x;
    const int n = blockIdx.y;
    const int t = threadIdx.x;
    const int wr = n >> 4, wc = n & 15;
    const int l_t = (wr * 4 + (t >> 5)) * W_IMG + wc * 32 + (t & 31);
    const int cbase = h * HD;

    sm.l[t]  = l_t;
    sm.px[t] = pos[(long)l_t * 2 + 0];
    sm.py[t] = pos[(long)l_t * 2 + 1];
    __syncthreads();

    for (int i = t; i < T_WIN * HD; i += T_WIN) {
        const int u = i >> 5, d = i & 31;
        const long base = (long)sm.l[u] * C_DIM + cbase + d;
        sm.K[u][d] = K[base];
        sm.V[u][d] = V[base];
    }

    float cA[16], cB[16], cC[16], cW[16];
    #pragma unroll
    for (int i = 0; i < 16; i++) {
        const float s = bn_g[i] * rsqrtf(bn_v[i] + EPS);
        cA[i] = pw1[2 * i + 0] * s;
        cB[i] = pw1[2 * i + 1] * s;
        cC[i] = (pb1[i] - bn_m[i]) * s + bn_b[i];
        cW[i] = pw2[h * 16 + i];
    }
    const float pb2h = pb2[h];
    __syncthreads();

    const float pxu = sm.px[t], pyu = sm.py[t];
    for (int tt = 0; tt < T_WIN; tt++) {
        const float dx = sm.px[tt] - pxu;
        const float dy = sm.py[tt] - pyu;
        float bsum = pb2h;
        #pragma unroll
        for (int i = 0; i < 16; i++) {
            float f = fmaf(cA[i], dx, fmaf(cB[i], dy, cC[i]));
            bsum = fmaf(cW[i], fmaxf(f, 0.f), bsum);
        }
        sm.S[tt][t] = bsum;
    }
    __syncthreads();

    float q[HD];
    #pragma unroll
    for (int d = 0; d < HD; d++) q[d] = Q[(long)l_t * C_DIM + cbase + d];

    float m = -1e30f;
    for (int u = 0; u < T_WIN; u++) {
        float s = sm.S[t][u];
        #pragma unroll
        for (int d = 0; d < HD; d++) s = fmaf(q[d], sm.K[u][d], s);
        sm.S[t][u] = s;
        m = fmaxf(m, s);
    }

    float rs = 0.f;
    for (int u = 0; u < T_WIN; u++) {
        const float p = __expf(sm.S[t][u] - m);
        sm.S[t][u] = p;
        rs += p;
    }
    const float inv = 1.f / rs;

    float acc[HD];
    #pragma unroll
    for (int d = 0; d < HD; d++) acc[d] = 0.f;
    for (int u = 0; u < T_WIN; u++) {
        const float p = sm.S[t][u];
        #pragma unroll
        for (int d = 0; d < HD; d++) acc[d] = fmaf(p, sm.V[u][d], acc[d]);
    }
    #pragma unroll
    for (int d = 0; d < HD; d++)
        O[(long)l_t * C_DIM + cbase + d] = __float2bfloat16(acc[d] * inv);
}

// ---------------- launch ----------------
extern "C" void kernel_launch(void* const* d_in, const int* in_sizes, int n_in,
                              void* d_out, int out_size)
{
    const float* x      = (const float*)d_in[0];
    const float* pos    = (const float*)d_in[1];
    const float* n1g    = (const float*)d_in[2];
    const float* n1b    = (const float*)d_in[3];
    const float* wq     = (const float*)d_in[4];
    const float* bq     = (const float*)d_in[5];
    const float* wk     = (const float*)d_in[6];
    const float* bk     = (const float*)d_in[7];
    const float* wv     = (const float*)d_in[8];
    const float* bv     = (const float*)d_in[9];
    const float* wo     = (const float*)d_in[10];
    const float* bo     = (const float*)d_in[11];
    const float* n2g    = (const float*)d_in[12];
    const float* n2b    = (const float*)d_in[13];
    const float* wfc1   = (const float*)d_in[14];
    const float* bfc1   = (const float*)d_in[15];
    const float* wfc2   = (const float*)d_in[16];
    const float* bfc2   = (const float*)d_in[17];
    const float* pw1    = (const float*)d_in[18];
    const float* pb1    = (const float*)d_in[19];
    const float* bn_g   = (const float*)d_in[20];
    const float* bn_b   = (const float*)d_in[21];
    const float* bn_m   = (const float*)d_in[22];
    const float* bn_v   = (const float*)d_in[23];
    const float* pw2    = (const float*)d_in[24];
    const float* pb2    = (const float*)d_in[25];
    float* out = (float*)d_out;

    float* base = nullptr;
    cudaGetSymbolAddress((void**)&base, g_scratch);
    bf16*  xn   = (bf16*)(base + 0 * SZ_LC);
    float* q    = base + 1 * SZ_LC;
    float* k    = base + 2 * SZ_LC;
    float* v    = base + 3 * SZ_LC;
    bf16*  o    = (bf16*)(base + 4 * SZ_LC);
    float* x1   = base + 5 * SZ_LC;
    bf16*  xn2  = (bf16*)(base + 6 * SZ_LC);
    bf16*  hid  = (bf16*)(base + 7 * SZ_LC);

    bf16* wbf = nullptr;
    cudaGetSymbolAddress((void**)&wbf, g_wbf);
    bf16* wq_b   = wbf + 0;
    bf16* wk_b   = wbf + 65536;
    bf16* wv_b   = wbf + 131072;
    bf16* wo_b   = wbf + 196608;
    bf16* wfc1_b = wbf + 262144;
    bf16* wfc2_b = wbf + 524288;

    cudaFuncSetAttribute(attn_kernel, cudaFuncAttributeMaxDynamicSharedMemorySize,
                         (int)sizeof(AttnSmem));

    // weight conversions
    f2bf_kernel<<<128, 256>>>(wq,   wq_b,   65536);
    f2bf_kernel<<<128, 256>>>(wk,   wk_b,   65536);
    f2bf_kernel<<<128, 256>>>(wv,   wv_b,   65536);
    f2bf_kernel<<<128, 256>>>(wo,   wo_b,   65536);
    f2bf_kernel<<<256, 256>>>(wfc1, wfc1_b, 262144);
    f2bf_kernel<<<256, 256>>>(wfc2, wfc2_b, 262144);

    // 1. xn = LN1(x)  (bf16)
    ln_kernel<<<L_TOK, 256>>>(x, n1g, n1b, xn);

    // 2-4. Q (scaled), K, V
    mma_gemm<0, false><<<dim3(C_DIM / 128, L_TOK / 128), 256>>>(
        xn, wq_b, bq, nullptr, q, L_TOK, C_DIM, C_DIM, SCALE);
    mma_gemm<0, false><<<dim3(C_DIM / 128, L_TOK / 128), 256>>>(
        xn, wk_b, bk, nullptr, k, L_TOK, C_DIM, C_DIM, 1.f);
    mma_gemm<0, false><<<dim3(C_DIM / 128, L_TOK / 128), 256>>>(
        xn, wv_b, bv, nullptr, v, L_TOK, C_DIM, C_DIM, 1.f);

    // 5. attention
    attn_kernel<<<dim3(NH, NW), T_WIN, sizeof(AttnSmem)>>>(
        q, k, v, pos, pw1, pb1, bn_g, bn_b, bn_m, bn_v, pw2, pb2, o);

    // 6. x1 = x + o @ wo + bo
    mma_gemm<1, false><<<dim3(C_DIM / 128, L_TOK / 128), 256>>>(
        o, wo_b, bo, x, x1, L_TOK, C_DIM, C_DIM, 1.f);

    // 7. xn2 = LN2(x1)
    ln_kernel<<<L_TOK, 256>>>(x1, n2g, n2b, xn2);

    // 8. hid = gelu(xn2 @ wfc1 + bfc1)  (bf16)
    mma_gemm<2, true><<<dim3(HID_DIM / 128, L_TOK / 128), 256>>>(
        xn2, wfc1_b, bfc1, nullptr, hid, L_TOK, HID_DIM, C_DIM, 1.f);

    // 9. out = x1 + hid @ wfc2 + bfc2
    mma_gemm<1, false><<<dim3(C_DIM / 128, L_TOK / 128), 256>>>(
        hid, wfc2_b, bfc2, x1, out, L_TOK, C_DIM, HID_DIM, 1.f);
}

// round 3
// speedup vs baseline: 4.6479x; 1.8318x over previous
#include <cuda_runtime.h>
#include <cuda_bf16.h>
#include <math.h>

using bf16 = __nv_bfloat16;

// ---------------- problem constants ----------------
#define L_TOK 32768
#define C_DIM 256
#define HID_DIM 1024
#define NW 256
#define NH 8
#define T_WIN 128
#define HD 32
#define W_IMG 512
#define EPS 1e-5f
#define SCALE 0.17677669529663687f

// ---------------- scratch ----------------
static const size_t SZ_LC = (size_t)L_TOK * C_DIM;
__device__ float g_scratch[8 * 8388608ull + (size_t)L_TOK * HID_DIM];
__device__ bf16  g_wbf[786432];   // wqkv(196608) | wo(65536) | wfc1(262144) | wfc2(262144)
__device__ float g_bqkv[768];

// ---------------- PTX helpers ----------------
__device__ __forceinline__ void cp16(unsigned saddr, const void* g)
{
    asm volatile("cp.async.cg.shared.global [%0], [%1], 16;" :: "r"(saddr), "l"(g));
}
__device__ __forceinline__ void ldsm4(unsigned* r, unsigned addr)
{
    asm volatile("ldmatrix.sync.aligned.m8n8.x4.shared.b16 {%0,%1,%2,%3}, [%4];"
                 : "=r"(r[0]), "=r"(r[1]), "=r"(r[2]), "=r"(r[3]) : "r"(addr));
}
__device__ __forceinline__ void ldsm4t(unsigned* r, unsigned addr)
{
    asm volatile("ldmatrix.sync.aligned.m8n8.x4.trans.shared.b16 {%0,%1,%2,%3}, [%4];"
                 : "=r"(r[0]), "=r"(r[1]), "=r"(r[2]), "=r"(r[3]) : "r"(addr));
}
__device__ __forceinline__ void mma16816(float* d, const unsigned* a, const unsigned* b)
{
    asm volatile("mma.sync.aligned.m16n8k16.row.col.f32.bf16.bf16.f32 "
                 "{%0,%1,%2,%3}, {%4,%5,%6,%7}, {%8,%9}, {%0,%1,%2,%3};"
                 : "+f"(d[0]), "+f"(d[1]), "+f"(d[2]), "+f"(d[3])
                 : "r"(a[0]), "r"(a[1]), "r"(a[2]), "r"(a[3]), "r"(b[0]), "r"(b[1]));
}
__device__ __forceinline__ unsigned packbf(float a, float b)
{
    __nv_bfloat162 h = __floats2bfloat162_rn(a, b);
    return *reinterpret_cast<unsigned*>(&h);
}

// ---------------- pack / convert weights ----------------
__global__ void pack_kernel(const float* __restrict__ wq, const float* __restrict__ wk,
                            const float* __restrict__ wv, const float* __restrict__ bq,
                            const float* __restrict__ bk, const float* __restrict__ bv,
                            const float* __restrict__ wo, const float* __restrict__ wfc1,
                            const float* __restrict__ wfc2)
{
    const int total = 786432 + 768;
    for (int i = blockIdx.x * blockDim.x + threadIdx.x; i < total; i += gridDim.x * blockDim.x) {
        if (i < 196608) {
            const int r = i / 768, c = i % 768;
            float v = (c < 256) ? wq[r * 256 + c] * SCALE
                    : (c < 512) ? wk[r * 256 + c - 256]
                                : wv[r * 256 + c - 512];
            g_wbf[i] = __float2bfloat16(v);
        } else if (i < 262144) {
            g_wbf[i] = __float2bfloat16(wo[i - 196608]);
        } else if (i < 524288) {
            g_wbf[i] = __float2bfloat16(wfc1[i - 262144]);
        } else if (i < 786432) {
            g_wbf[i] = __float2bfloat16(wfc2[i - 524288]);
        } else {
            const int c = i - 786432;
            g_bqkv[c] = (c < 256) ? bq[c] * SCALE : (c < 512) ? bk[c - 256] : bv[c - 512];
        }
    }
}

// ---------------- LayerNorm (bf16 output) ----------------
__global__ void ln_kernel(const float* __restrict__ x,
                          const float* __restrict__ g,
                          const float* __restrict__ b,
                          bf16* __restrict__ y)
{
    const int row = blockIdx.x;
    const int tid = threadIdx.x;
    const float v = x[(long)row * C_DIM + tid];

    float s = v, sq = v * v;
    #pragma unroll
    for (int o = 16; o > 0; o >>= 1) {
        s  += __shfl_xor_sync(0xffffffffu, s, o);
        sq += __shfl_xor_sync(0xffffffffu, sq, o);
    }
    __shared__ float ss[8], ssq[8];
    if ((tid & 31) == 0) { ss[tid >> 5] = s; ssq[tid >> 5] = sq; }
    __syncthreads();
    float S = 0.f, SQ = 0.f;
    #pragma unroll
    for (int i = 0; i < 8; i++) { S += ss[i]; SQ += ssq[i]; }
    const float mean = S * (1.f / 256.f);
    const float var  = SQ * (1.f / 256.f) - mean * mean;
    const float inv  = rsqrtf(var + EPS);
    y[(long)row * C_DIM + tid] = __float2bfloat16((v - mean) * inv * g[tid] + b[tid]);
}

// ---------------- tensor-core GEMM (3-stage cp.async, K-chunk 64) ----------------
#define A_STRIDE 72
#define B_STRIDE 136
#define KCH 64
#define GEMM_SMEM ((3 * (128 * A_STRIDE + 64 * B_STRIDE)) * 2)

template<int OP, bool BF_OUT>
__global__ __launch_bounds__(256, 2)
void mma_gemm(const bf16* __restrict__ A, const bf16* __restrict__ B,
              const float* __restrict__ bias, const float* __restrict__ R,
              void* __restrict__ Cout, int M, int N, int K, float scale)
{
    extern __shared__ bf16 smem[];
    const int A_ST = 128 * A_STRIDE;
    const int B_ST = 64 * B_STRIDE;
    bf16* As = smem;
    bf16* Bs = smem + 3 * A_ST;

    const int tid  = threadIdx.x;
    const int lane = tid & 31;
    const int wid  = tid >> 5;
    const int wm   = wid >> 1;
    const int wn   = wid & 1;
    const int m0   = blockIdx.y * 128;
    const int n0   = blockIdx.x * 128;

    const unsigned asb = (unsigned)__cvta_generic_to_shared(As);
    const unsigned bsb = (unsigned)__cvta_generic_to_shared(Bs);

    auto issue = [&](int kt, int s) {
        const int kb = kt * KCH;
        #pragma unroll
        for (int p = 0; p < 4; p++) {
            const int id = tid + 256 * p;
            const int ar = id >> 3, ac = id & 7;
            cp16(asb + (s * A_ST + ar * A_STRIDE + ac * 8) * 2,
                 A + (long)(m0 + ar) * K + kb + ac * 8);
        }
        #pragma unroll
        for (int p = 0; p < 4; p++) {
            const int id = tid + 256 * p;
            const int br = id >> 4, bc = id & 15;
            cp16(bsb + (s * B_ST + br * B_STRIDE + bc * 8) * 2,
                 B + (long)(kb + br) * N + n0 + bc * 8);
        }
        asm volatile("cp.async.commit_group;");
    };

    const int mat = lane >> 3, r8 = lane & 7;
    const int a_row = wm * 32 + (mat & 1) * 8 + r8;
    const int a_col = (mat >> 1) * 8;
    const int b_kr  = (mat & 1) * 8 + r8;
    const int b_nc  = wn * 64 + (mat >> 1) * 8;

    float acc[2][8][4];
    #pragma unroll
    for (int i = 0; i < 2; i++)
        #pragma unroll
        for (int j = 0; j < 8; j++)
            #pragma unroll
            for (int q = 0; q < 4; q++) acc[i][j][q] = 0.f;

    const int KT = K / KCH;
    issue(0, 0);
    issue(1, 1);

    for (int kt = 0; kt < KT; kt++) {
        if (kt + 1 < KT) asm volatile("cp.async.wait_group %0;" :: "n"(1));
        else             asm volatile("cp.async.wait_group %0;" :: "n"(0));
        __syncthreads();
        if (kt + 2 < KT) issue(kt + 2, (kt + 2) % 3);

        const int s = kt % 3;
        #pragma unroll
        for (int ks = 0; ks < 4; ks++) {
            unsigned a[2][4], b[4][4];
            #pragma unroll
            for (int mt = 0; mt < 2; mt++)
                ldsm4(a[mt], asb + ((s * A_ST) + (a_row + mt * 16) * A_STRIDE + a_col + ks * 16) * 2);
            #pragma unroll
            for (int nt = 0; nt < 4; nt++)
                ldsm4t(b[nt], bsb + ((s * B_ST) + (b_kr + ks * 16) * B_STRIDE + b_nc + nt * 16) * 2);
            #pragma unroll
            for (int mt = 0; mt < 2; mt++)
                #pragma unroll
                for (int n8 = 0; n8 < 8; n8++)
                    mma16816(acc[mt][n8], a[mt], &b[n8 >> 1][(n8 & 1) * 2]);
        }
    }

    const int gr = lane >> 2, tig = lane & 3;
    #pragma unroll
    for (int mt = 0; mt < 2; mt++) {
        #pragma unroll
        for (int n8 = 0; n8 < 8; n8++) {
            const int col = n0 + wn * 64 + n8 * 8 + tig * 2;
            const float b0 = bias[col], b1 = bias[col + 1];
            #pragma unroll
            for (int half = 0; half < 2; half++) {
                const int row = m0 + wm * 32 + mt * 16 + gr + half * 8;
                float v0 = acc[mt][n8][half * 2 + 0] + b0;
                float v1 = acc[mt][n8][half * 2 + 1] + b1;
                if (OP == 0) { v0 *= scale; v1 *= scale; }
                if (OP == 1) {
                    const float2 rr = *reinterpret_cast<const float2*>(R + (long)row * N + col);
                    v0 += rr.x; v1 += rr.y;
                }
                if (OP == 2) {
                    v0 = 0.5f * v0 * (1.f + erff(v0 * 0.70710678118654752f));
                    v1 = 0.5f * v1 * (1.f + erff(v1 * 0.70710678118654752f));
                }
                if (BF_OUT) {
                    bf16* C = (bf16*)Cout;
                    __nv_bfloat162 p = __floats2bfloat162_rn(v0, v1);
                    *reinterpret_cast<__nv_bfloat162*>(C + (long)row * N + col) = p;
                } else {
                    float* C = (float*)Cout;
                    *reinterpret_cast<float2*>(C + (long)row * N + col) = make_float2(v0, v1);
                }
            }
        }
    }
}

// ---------------- fused windowed attention (tensor core) ----------------
#define QKV_N 768
#define QS_STRIDE 40

struct AttnSmem {
    float Sb[T_WIN][T_WIN + 4];        // bias tile, 128x132
    bf16  Qs[T_WIN * QS_STRIDE];
    bf16  Ks[T_WIN * QS_STRIDE];
    bf16  Vs[T_WIN * QS_STRIDE];
    float sfeat[T_WIN][20];
    float px[T_WIN], py[T_WIN];
};

__global__ __launch_bounds__(128)
void attn_kernel(const bf16* __restrict__ qkv, const float* __restrict__ pos,
                 const float* __restrict__ pw1, const float* __restrict__ pb1,
                 const float* __restrict__ bn_g, const float* __restrict__ bn_b,
                 const float* __restrict__ bn_m, const float* __restrict__ bn_v,
                 const float* __restrict__ pw2, const float* __restrict__ pb2,
                 bf16* __restrict__ O)
{
    extern __shared__ char sraw[];
    AttnSmem& sm = *reinterpret_cast<AttnSmem*>(sraw);

    const int h = blockIdx.x, n = blockIdx.y;
    const int t = threadIdx.x, lane = t & 31, warp = t >> 5;
    const int wr = n >> 4, wc = n & 15;
    const int l_t = (wr * 4 + (t >> 5)) * W_IMG + wc * 32 + (t & 31);

    const float2 p2 = *reinterpret_cast<const float2*>(pos + (long)l_t * 2);
    sm.px[t] = p2.x; sm.py[t] = p2.y;

    // async Q/K/V tile loads (each thread owns its own token row)
    const unsigned qb = (unsigned)__cvta_generic_to_shared(sm.Qs);
    const unsigned kb = (unsigned)__cvta_generic_to_shared(sm.Ks);
    const unsigned vb = (unsigned)__cvta_generic_to_shared(sm.Vs);
    const bf16* grow = qkv + (long)l_t * QKV_N + h * HD;
    #pragma unroll
    for (int c = 0; c < 4; c++) {
        cp16(qb + (t * QS_STRIDE + c * 8) * 2, grow + c * 8);
        cp16(kb + (t * QS_STRIDE + c * 8) * 2, grow + 256 + c * 8);
        cp16(vb + (t * QS_STRIDE + c * 8) * 2, grow + 512 + c * 8);
    }
    asm volatile("cp.async.commit_group;");

    // fused conv1+BN features: s_i[l] = a_i*px + b_i*py ; bias = sum w_i relu(s_i[t]-s_i[u]+c_i)
    float cu[16], cW[16];
    #pragma unroll
    for (int i = 0; i < 16; i++) {
        const float sc = bn_g[i] * rsqrtf(bn_v[i] + EPS);
        const float a  = pw1[2 * i] * sc, bcoef = pw1[2 * i + 1] * sc;
        const float c0 = (pb1[i] - bn_m[i]) * sc + bn_b[i];
        const float si = a * p2.x + bcoef * p2.y;
        sm.sfeat[t][i] = si;
        cu[i] = c0 - si;                 // column-u term folded
        cW[i] = pw2[h * 16 + i];
    }
    const float pb2h = pb2[h];
    __syncthreads();

    // phase A: bias column u = t into Sb
    for (int tt = 0; tt < T_WIN; tt++) {
        float sf[16];
        *reinterpret_cast<float4*>(&sf[0])  = *reinterpret_cast<const float4*>(&sm.sfeat[tt][0]);
        *reinterpret_cast<float4*>(&sf[4])  = *reinterpret_cast<const float4*>(&sm.sfeat[tt][4]);
        *reinterpret_cast<float4*>(&sf[8])  = *reinterpret_cast<const float4*>(&sm.sfeat[tt][8]);
        *reinterpret_cast<float4*>(&sf[12]) = *reinterpret_cast<const float4*>(&sm.sfeat[tt][12]);
        float s = pb2h;
        #pragma unroll
        for (int i = 0; i < 16; i++)
            s = fmaf(cW[i], fmaxf(sf[i] + cu[i], 0.f), s);
        sm.Sb[tt][t] = s;
    }

    asm volatile("cp.async.wait_group 0;");
    __syncthreads();

    // S = Q @ K^T  (warp owns 32 query rows x all 128 key cols)
    const int mat = lane >> 3, r8 = lane & 7;
    float acc[2][16][4];
    #pragma unroll
    for (int i = 0; i < 2; i++)
        #pragma unroll
        for (int j = 0; j < 16; j++)
            #pragma unroll
            for (int q = 0; q < 4; q++) acc[i][j][q] = 0.f;

    #pragma unroll
    for (int ks = 0; ks < 2; ks++) {
        unsigned a[2][4];
        #pragma unroll
        for (int mt = 0; mt < 2; mt++)
            ldsm4(a[mt], qb + ((warp * 32 + mt * 16 + (mat & 1) * 8 + r8) * QS_STRIDE
                               + (mat >> 1) * 8 + ks * 16) * 2);
        #pragma unroll
        for (int nt = 0; nt < 8; nt++) {
            unsigned bfr[4];
            ldsm4(bfr, kb + ((nt * 16 + (mat >> 1) * 8 + r8) * QS_STRIDE
                             + (mat & 1) * 8 + ks * 16) * 2);
            #pragma unroll
            for (int mt = 0; mt < 2; mt++) {
                mma16816(acc[mt][2 * nt + 0], a[mt], &bfr[0]);
                mma16816(acc[mt][2 * nt + 1], a[mt], &bfr[2]);
            }
        }
    }

    // bias add + softmax (unnormalized; scale folded after PV)
    const int gr = lane >> 2, tig = lane & 3;
    float inv[2][2];
    #pragma unroll
    for (int mt = 0; mt < 2; mt++) {
        #pragma unroll
        for (int hf = 0; hf < 2; hf++) {
            const int row = warp * 32 + mt * 16 + gr + hf * 8;
            float m = -1e30f;
            #pragma unroll
            for (int j = 0; j < 16; j++) {
                const float2 bb = *reinterpret_cast<const float2*>(&sm.Sb[row][j * 8 + tig * 2]);
                float v0 = acc[mt][j][hf * 2 + 0] + bb.x;
                float v1 = acc[mt][j][hf * 2 + 1] + bb.y;
                acc[mt][j][hf * 2 + 0] = v0;
                acc[mt][j][hf * 2 + 1] = v1;
                m = fmaxf(m, fmaxf(v0, v1));
            }
            m = fmaxf(m, __shfl_xor_sync(0xffffffffu, m, 1));
            m = fmaxf(m, __shfl_xor_sync(0xffffffffu, m, 2));
            float rs = 0.f;
            #pragma unroll
            for (int j = 0; j < 16; j++) {
                const float p0 = __expf(acc[mt][j][hf * 2 + 0] - m);
                const float p1 = __expf(acc[mt][j][hf * 2 + 1] - m);
                acc[mt][j][hf * 2 + 0] = p0;
                acc[mt][j][hf * 2 + 1] = p1;
                rs += p0 + p1;
            }
            rs += __shfl_xor_sync(0xffffffffu, rs, 1);
            rs += __shfl_xor_sync(0xffffffffu, rs, 2);
            inv[mt][hf] = 1.f / rs;
        }
    }

    // O = P @ V  (P straight from registers)
    float oacc[2][4][4];
    #pragma unroll
    for (int i = 0; i < 2; i++)
        #pragma unroll
        for (int j = 0; j < 4; j++)
            #pragma unroll
            for (int q = 0; q < 4; q++) oacc[i][j][q] = 0.f;

    #pragma unroll
    for (int kk = 0; kk < 8; kk++) {
        unsigned ap[2][4];
        #pragma unroll
        for (int mt = 0; mt < 2; mt++) {
            ap[mt][0] = packbf(acc[mt][2 * kk][0],     acc[mt][2 * kk][1]);
            ap[mt][1] = packbf(acc[mt][2 * kk][2],     acc[mt][2 * kk][3]);
            ap[mt][2] = packbf(acc[mt][2 * kk + 1][0], acc[mt][2 * kk + 1][1]);
            ap[mt][3] = packbf(acc[mt][2 * kk + 1][2], acc[mt][2 * kk + 1][3]);
        }
        #pragma unroll
        for (int vt = 0; vt < 2; vt++) {
            unsigned bv[4];
            ldsm4t(bv, vb + ((kk * 16 + (mat & 1) * 8 + r8) * QS_STRIDE
                             + (mat >> 1) * 8 + vt * 16) * 2);
            #pragma unroll
            for (int mt = 0; mt < 2; mt++) {
                mma16816(oacc[mt][2 * vt + 0], ap[mt], &bv[0]);
                mma16816(oacc[mt][2 * vt + 1], ap[mt], &bv[2]);
            }
        }
    }

    // write O (normalize per-row)
    #pragma unroll
    for (int mt = 0; mt < 2; mt++) {
        #pragma unroll
        for (int hf = 0; hf < 2; hf++) {
            const int row  = warp * 32 + mt * 16 + gr + hf * 8;
            const int lrow = (wr * 4 + (row >> 5)) * W_IMG + wc * 32 + (row & 31);
            bf16* orow = O + (long)lrow * C_DIM + h * HD;
            const float sc = inv[mt][hf];
            #pragma unroll
            for (int j = 0; j < 4; j++) {
                __nv_bfloat162 pr = __floats2bfloat162_rn(oacc[mt][j][hf * 2 + 0] * sc,
                                                          oacc[mt][j][hf * 2 + 1] * sc);
                *reinterpret_cast<__nv_bfloat162*>(orow + j * 8 + tig * 2) = pr;
            }
        }
    }
}

// ---------------- launch ----------------
extern "C" void kernel_launch(void* const* d_in, const int* in_sizes, int n_in,
                              void* d_out, int out_size)
{
    const float* x      = (const float*)d_in[0];
    const float* pos    = (const float*)d_in[1];
    const float* n1g    = (const float*)d_in[2];
    const float* n1b    = (const float*)d_in[3];
    const float* wq     = (const float*)d_in[4];
    const float* bq     = (const float*)d_in[5];
    const float* wk     = (const float*)d_in[6];
    const float* bk     = (const float*)d_in[7];
    const float* wv     = (const float*)d_in[8];
    const float* bv     = (const float*)d_in[9];
    const float* wo     = (const float*)d_in[10];
    const float* bo     = (const float*)d_in[11];
    const float* n2g    = (const float*)d_in[12];
    const float* n2b    = (const float*)d_in[13];
    const float* wfc1   = (const float*)d_in[14];
    const float* bfc1   = (const float*)d_in[15];
    const float* wfc2   = (const float*)d_in[16];
    const float* bfc2   = (const float*)d_in[17];
    const float* pw1    = (const float*)d_in[18];
    const float* pb1    = (const float*)d_in[19];
    const float* bn_g   = (const float*)d_in[20];
    const float* bn_b   = (const float*)d_in[21];
    const float* bn_m   = (const float*)d_in[22];
    const float* bn_v   = (const float*)d_in[23];
    const float* pw2    = (const float*)d_in[24];
    const float* pb2    = (const float*)d_in[25];
    float* out = (float*)d_out;

    float* base = nullptr;
    cudaGetSymbolAddress((void**)&base, g_scratch);
    bf16*  xn   = (bf16*)(base + 0 * SZ_LC);
    bf16*  qkv  = (bf16*)(base + 1 * SZ_LC);     // slots 1-2 (L x 768 bf16)
    bf16*  o    = (bf16*)(base + 3 * SZ_LC);
    float* x1   = base + 4 * SZ_LC;
    bf16*  xn2  = (bf16*)(base + 5 * SZ_LC);
    bf16*  hid  = (bf16*)(base + 6 * SZ_LC);     // slots 6-7 (L x 1024 bf16)

    bf16* wbf = nullptr;
    cudaGetSymbolAddress((void**)&wbf, g_wbf);
    bf16* wqkv_b = wbf + 0;
    bf16* wo_b   = wbf + 196608;
    bf16* wfc1_b = wbf + 262144;
    bf16* wfc2_b = wbf + 524288;
    float* bqkv = nullptr;
    cudaGetSymbolAddress((void**)&bqkv, g_bqkv);

    cudaFuncSetAttribute(mma_gemm<0, true>,  cudaFuncAttributeMaxDynamicSharedMemorySize, GEMM_SMEM);
    cudaFuncSetAttribute(mma_gemm<1, false>, cudaFuncAttributeMaxDynamicSharedMemorySize, GEMM_SMEM);
    cudaFuncSetAttribute(mma_gemm<2, true>,  cudaFuncAttributeMaxDynamicSharedMemorySize, GEMM_SMEM);
    cudaFuncSetAttribute(attn_kernel, cudaFuncAttributeMaxDynamicSharedMemorySize, (int)sizeof(AttnSmem));

    // 0. pack all weights to bf16 (q-scale folded)
    pack_kernel<<<768, 256>>>(wq, wk, wv, bq, bk, bv, wo, wfc1, wfc2);

    // 1. xn = LN1(x)
    ln_kernel<<<L_TOK, 256>>>(x, n1g, n1b, xn);

    // 2. qkv = xn @ wqkv + bqkv   (q pre-scaled)
    mma_gemm<0, true><<<dim3(QKV_N / 128, L_TOK / 128), 256, GEMM_SMEM>>>(
        xn, wqkv_b, bqkv, nullptr, qkv, L_TOK, QKV_N, C_DIM, 1.f);

    // 3. attention
    attn_kernel<<<dim3(NH, NW), T_WIN, sizeof(AttnSmem)>>>(
        qkv, pos, pw1, pb1, bn_g, bn_b, bn_m, bn_v, pw2, pb2, o);

    // 4. x1 = x + o @ wo + bo
    mma_gemm<1, false><<<dim3(C_DIM / 128, L_TOK / 128), 256, GEMM_SMEM>>>(
        o, wo_b, bo, x, x1, L_TOK, C_DIM, C_DIM, 1.f);

    // 5. xn2 = LN2(x1)
    ln_kernel<<<L_TOK, 256>>>(x1, n2g, n2b, xn2);

    // 6. hid = gelu(xn2 @ wfc1 + bfc1)
    mma_gemm<2, true><<<dim3(HID_DIM / 128, L_TOK / 128), 256, GEMM_SMEM>>>(
        xn2, wfc1_b, bfc1, nullptr, hid, L_TOK, HID_DIM, C_DIM, 1.f);

    // 7. out = x1 + hid @ wfc2 + bfc2
    mma_gemm<1, false><<<dim3(C_DIM / 128, L_TOK / 128), 256, GEMM_SMEM>>>(
        hid, wfc2_b, bfc2, x1, out, L_TOK, C_DIM, HID_DIM, 1.f);
}

// round 4
// speedup vs baseline: 5.0954x; 1.0963x over previous
#include <cuda_runtime.h>
#include <cuda_bf16.h>
#include <math.h>

using bf16 = __nv_bfloat16;

// ---------------- problem constants ----------------
#define L_TOK 32768
#define C_DIM 256
#define HID_DIM 1024
#define NW 256
#define NH 8
#define T_WIN 128
#define HD 32
#define W_IMG 512
#define EPS 1e-5f
#define SCALE 0.17677669529663687f
#define QKV_N 768

// ---------------- scratch ----------------
static const size_t SZ_LC = (size_t)L_TOK * C_DIM;
__device__ float g_scratch[8 * 8388608ull + (size_t)L_TOK * HID_DIM];
__device__ bf16  g_wbf[786432];   // wqkv(196608) | wo(65536) | wfc1(262144) | wfc2(262144)
__device__ float g_bqkv[768];

// ---------------- PTX helpers ----------------
__device__ __forceinline__ void cp16(unsigned saddr, const void* g)
{
    asm volatile("cp.async.cg.shared.global [%0], [%1], 16;" :: "r"(saddr), "l"(g));
}
__device__ __forceinline__ void ldsm4(unsigned* r, unsigned addr)
{
    asm volatile("ldmatrix.sync.aligned.m8n8.x4.shared.b16 {%0,%1,%2,%3}, [%4];"
                 : "=r"(r[0]), "=r"(r[1]), "=r"(r[2]), "=r"(r[3]) : "r"(addr));
}
__device__ __forceinline__ void ldsm4t(unsigned* r, unsigned addr)
{
    asm volatile("ldmatrix.sync.aligned.m8n8.x4.trans.shared.b16 {%0,%1,%2,%3}, [%4];"
                 : "=r"(r[0]), "=r"(r[1]), "=r"(r[2]), "=r"(r[3]) : "r"(addr));
}
__device__ __forceinline__ void mma16816(float* d, const unsigned* a, const unsigned* b)
{
    asm volatile("mma.sync.aligned.m16n8k16.row.col.f32.bf16.bf16.f32 "
                 "{%0,%1,%2,%3}, {%4,%5,%6,%7}, {%8,%9}, {%0,%1,%2,%3};"
                 : "+f"(d[0]), "+f"(d[1]), "+f"(d[2]), "+f"(d[3])
                 : "r"(a[0]), "r"(a[1]), "r"(a[2]), "r"(a[3]), "r"(b[0]), "r"(b[1]));
}
__device__ __forceinline__ unsigned packbf(float a, float b)
{
    __nv_bfloat162 h = __floats2bfloat162_rn(a, b);
    return *reinterpret_cast<unsigned*>(&h);
}

// ---------------- pack / convert weights ----------------
__global__ void pack_kernel(const float* __restrict__ wq, const float* __restrict__ wk,
                            const float* __restrict__ wv, const float* __restrict__ bq,
                            const float* __restrict__ bk, const float* __restrict__ bv,
                            const float* __restrict__ wo, const float* __restrict__ wfc1,
                            const float* __restrict__ wfc2)
{
    const int total = 786432 + 768;
    for (int i = blockIdx.x * blockDim.x + threadIdx.x; i < total; i += gridDim.x * blockDim.x) {
        if (i < 196608) {
            const int r = i / 768, c = i % 768;
            float v = (c < 256) ? wq[r * 256 + c] * SCALE
                    : (c < 512) ? wk[r * 256 + c - 256]
                                : wv[r * 256 + c - 512];
            g_wbf[i] = __float2bfloat16(v);
        } else if (i < 262144) {
            g_wbf[i] = __float2bfloat16(wo[i - 196608]);
        } else if (i < 524288) {
            g_wbf[i] = __float2bfloat16(wfc1[i - 262144]);
        } else if (i < 786432) {
            g_wbf[i] = __float2bfloat16(wfc2[i - 524288]);
        } else {
            const int c = i - 786432;
            g_bqkv[c] = (c < 256) ? bq[c] * SCALE : (c < 512) ? bk[c - 256] : bv[c - 512];
        }
    }
}

// ---------------- LayerNorm (bf16 output) ----------------
__global__ void ln_kernel(const float* __restrict__ x,
                          const float* __restrict__ g,
                          const float* __restrict__ b,
                          bf16* __restrict__ y)
{
    const int row = blockIdx.x;
    const int tid = threadIdx.x;
    const float v = x[(long)row * C_DIM + tid];

    float s = v, sq = v * v;
    #pragma unroll
    for (int o = 16; o > 0; o >>= 1) {
        s  += __shfl_xor_sync(0xffffffffu, s, o);
        sq += __shfl_xor_sync(0xffffffffu, sq, o);
    }
    __shared__ float ss[8], ssq[8];
    if ((tid & 31) == 0) { ss[tid >> 5] = s; ssq[tid >> 5] = sq; }
    __syncthreads();
    float S = 0.f, SQ = 0.f;
    #pragma unroll
    for (int i = 0; i < 8; i++) { S += ss[i]; SQ += ssq[i]; }
    const float mean = S * (1.f / 256.f);
    const float var  = SQ * (1.f / 256.f) - mean * mean;
    const float inv  = rsqrtf(var + EPS);
    y[(long)row * C_DIM + tid] = __float2bfloat16((v - mean) * inv * g[tid] + b[tid]);
}

// ---------------- tensor-core GEMM (3-stage cp.async, K-chunk 64) ----------------
#define A_STRIDE 72
#define B_STRIDE 136
#define KCH 64
#define GEMM_SMEM ((3 * (128 * A_STRIDE + 64 * B_STRIDE)) * 2)

template<int OP, bool BF_OUT>
__global__ __launch_bounds__(256, 2)
void mma_gemm(const bf16* __restrict__ A, const bf16* __restrict__ B,
              const float* __restrict__ bias, const float* __restrict__ R,
              void* __restrict__ Cout, int M, int N, int K, float scale)
{
    extern __shared__ bf16 smem[];
    const int A_ST = 128 * A_STRIDE;
    const int B_ST = 64 * B_STRIDE;
    bf16* As = smem;
    bf16* Bs = smem + 3 * A_ST;

    const int tid  = threadIdx.x;
    const int lane = tid & 31;
    const int wid  = tid >> 5;
    const int wm   = wid >> 1;
    const int wn   = wid & 1;
    const int m0   = blockIdx.y * 128;
    const int n0   = blockIdx.x * 128;

    const unsigned asb = (unsigned)__cvta_generic_to_shared(As);
    const unsigned bsb = (unsigned)__cvta_generic_to_shared(Bs);

    auto issue = [&](int kt, int s) {
        const int kb = kt * KCH;
        #pragma unroll
        for (int p = 0; p < 4; p++) {
            const int id = tid + 256 * p;
            const int ar = id >> 3, ac = id & 7;
            cp16(asb + (s * A_ST + ar * A_STRIDE + ac * 8) * 2,
                 A + (long)(m0 + ar) * K + kb + ac * 8);
        }
        #pragma unroll
        for (int p = 0; p < 4; p++) {
            const int id = tid + 256 * p;
            const int br = id >> 4, bc = id & 15;
            cp16(bsb + (s * B_ST + br * B_STRIDE + bc * 8) * 2,
                 B + (long)(kb + br) * N + n0 + bc * 8);
        }
        asm volatile("cp.async.commit_group;");
    };

    const int mat = lane >> 3, r8 = lane & 7;
    const int a_row = wm * 32 + (mat & 1) * 8 + r8;
    const int a_col = (mat >> 1) * 8;
    const int b_kr  = (mat & 1) * 8 + r8;
    const int b_nc  = wn * 64 + (mat >> 1) * 8;

    float acc[2][8][4];
    #pragma unroll
    for (int i = 0; i < 2; i++)
        #pragma unroll
        for (int j = 0; j < 8; j++)
            #pragma unroll
            for (int q = 0; q < 4; q++) acc[i][j][q] = 0.f;

    const int KT = K / KCH;
    issue(0, 0);
    issue(1, 1);

    for (int kt = 0; kt < KT; kt++) {
        if (kt + 1 < KT) asm volatile("cp.async.wait_group %0;" :: "n"(1));
        else             asm volatile("cp.async.wait_group %0;" :: "n"(0));
        __syncthreads();
        if (kt + 2 < KT) issue(kt + 2, (kt + 2) % 3);

        const int s = kt % 3;
        #pragma unroll
        for (int ks = 0; ks < 4; ks++) {
            unsigned a[2][4], b[4][4];
            #pragma unroll
            for (int mt = 0; mt < 2; mt++)
                ldsm4(a[mt], asb + ((s * A_ST) + (a_row + mt * 16) * A_STRIDE + a_col + ks * 16) * 2);
            #pragma unroll
            for (int nt = 0; nt < 4; nt++)
                ldsm4t(b[nt], bsb + ((s * B_ST) + (b_kr + ks * 16) * B_STRIDE + b_nc + nt * 16) * 2);
            #pragma unroll
            for (int mt = 0; mt < 2; mt++)
                #pragma unroll
                for (int n8 = 0; n8 < 8; n8++)
                    mma16816(acc[mt][n8], a[mt], &b[n8 >> 1][(n8 & 1) * 2]);
        }
    }

    const int gr = lane >> 2, tig = lane & 3;
    #pragma unroll
    for (int mt = 0; mt < 2; mt++) {
        #pragma unroll
        for (int n8 = 0; n8 < 8; n8++) {
            const int col = n0 + wn * 64 + n8 * 8 + tig * 2;
            const float b0 = bias[col], b1 = bias[col + 1];
            #pragma unroll
            for (int half = 0; half < 2; half++) {
                const int row = m0 + wm * 32 + mt * 16 + gr + half * 8;
                float v0 = acc[mt][n8][half * 2 + 0] + b0;
                float v1 = acc[mt][n8][half * 2 + 1] + b1;
                if (OP == 0) { v0 *= scale; v1 *= scale; }
                if (OP == 1) {
                    const float2 rr = *reinterpret_cast<const float2*>(R + (long)row * N + col);
                    v0 += rr.x; v1 += rr.y;
                }
                if (OP == 2) {
                    v0 = 0.5f * v0 * (1.f + erff(v0 * 0.70710678118654752f));
                    v1 = 0.5f * v1 * (1.f + erff(v1 * 0.70710678118654752f));
                }
                if (BF_OUT) {
                    bf16* C = (bf16*)Cout;
                    __nv_bfloat162 p = __floats2bfloat162_rn(v0, v1);
                    *reinterpret_cast<__nv_bfloat162*>(C + (long)row * N + col) = p;
                } else {
                    float* C = (float*)Cout;
                    *reinterpret_cast<float2*>(C + (long)row * N + col) = make_float2(v0, v1);
                }
            }
        }
    }
}

// ---------------- bias kernel: all 8 heads per window, tensor-core contraction ----------------
// bias[h][t][u] = pb2[h] + sum_i pw2[h,i] * relu(s_i[t] - s_i[u] + c0_i)
// mma m16n8k16: A = pw2 (heads x feats, rows 8..15 zero), B = hinge feats (feats x 8 u's)
// D: row = head, col = u-pair -> packed bf16x2 store.
__global__ __launch_bounds__(256)
void bias_kernel(const float* __restrict__ pos,
                 const float* __restrict__ pw1, const float* __restrict__ pb1,
                 const float* __restrict__ bn_g, const float* __restrict__ bn_b,
                 const float* __restrict__ bn_m, const float* __restrict__ bn_v,
                 const float* __restrict__ pw2, const float* __restrict__ pb2,
                 bf16* __restrict__ Bias)
{
    __shared__ float sfeat[T_WIN][20];

    const int n    = blockIdx.x;
    const int tid  = threadIdx.x;
    const int lane = tid & 31;
    const int warp = tid >> 5;
    const int gr   = lane >> 2;
    const int tig  = lane & 3;
    const int wr   = n >> 4, wc = n & 15;

    // per-token features s_i[l] (threads 0..127)
    if (tid < 128) {
        const int l_t = (wr * 4 + (tid >> 5)) * W_IMG + wc * 32 + (tid & 31);
        const float2 p2 = *reinterpret_cast<const float2*>(pos + (long)l_t * 2);
        #pragma unroll
        for (int i = 0; i < 16; i++) {
            const float sc = bn_g[i] * rsqrtf(bn_v[i] + EPS);
            sfeat[tid][i] = sc * (pw1[2 * i] * p2.x + pw1[2 * i + 1] * p2.y);
        }
    }

    // per-thread constants: feature indices k = {2tig, 2tig+1, 2tig+8, 2tig+9}
    float c0[4];
    const int kk0 = 2 * tig, kk1 = 2 * tig + 1, kk2 = 2 * tig + 8, kk3 = 2 * tig + 9;
    {
        const int ks[4] = {kk0, kk1, kk2, kk3};
        #pragma unroll
        for (int e = 0; e < 4; e++) {
            const int i = ks[e];
            const float sc = bn_g[i] * rsqrtf(bn_v[i] + EPS);
            c0[e] = sc * (pb1[i] - bn_m[i]) + bn_b[i];
        }
    }
    unsigned aw[4];
    aw[0] = packbf(pw2[gr * 16 + kk0], pw2[gr * 16 + kk1]);
    aw[2] = packbf(pw2[gr * 16 + kk2], pw2[gr * 16 + kk3]);
    aw[1] = 0; aw[3] = 0;
    const float pb2g = pb2[gr];
    __syncthreads();

    // warp handles 16 t-rows
    #pragma unroll 1
    for (int tt = 0; tt < 16; tt++) {
        const int t = warp * 16 + tt;
        const float ct0 = sfeat[t][kk0] + c0[0];
        const float ct1 = sfeat[t][kk1] + c0[1];
        const float ct2 = sfeat[t][kk2] + c0[2];
        const float ct3 = sfeat[t][kk3] + c0[3];
        bf16* orow = Bias + ((long)(gr * NW + n) * T_WIN + t) * T_WIN;

        #pragma unroll
        for (int u0 = 0; u0 < T_WIN; u0 += 8) {
            const int u = u0 + gr;
            const float f0 = fmaxf(ct0 - sfeat[u][kk0], 0.f);
            const float f1 = fmaxf(ct1 - sfeat[u][kk1], 0.f);
            const float f2 = fmaxf(ct2 - sfeat[u][kk2], 0.f);
            const float f3 = fmaxf(ct3 - sfeat[u][kk3], 0.f);
            unsigned bfr[2] = { packbf(f0, f1), packbf(f2, f3) };
            float d[4] = { pb2g, pb2g, 0.f, 0.f };
            mma16816(d, aw, bfr);
            *reinterpret_cast<__nv_bfloat162*>(orow + u0 + 2 * tig) =
                __floats2bfloat162_rn(d[0], d[1]);
        }
    }
}

// ---------------- slim windowed attention ----------------
#define QS_STRIDE 40
#define BS_STRIDE 136

struct AttnSmem {
    bf16 Qs[T_WIN * QS_STRIDE];
    bf16 Ks[T_WIN * QS_STRIDE];
    bf16 Vs[T_WIN * QS_STRIDE];
    bf16 Bs[T_WIN * BS_STRIDE];
};

__global__ __launch_bounds__(256, 2)
void attn_kernel(const bf16* __restrict__ qkv, const bf16* __restrict__ Bias,
                 bf16* __restrict__ O)
{
    extern __shared__ char sraw[];
    AttnSmem& sm = *reinterpret_cast<AttnSmem*>(sraw);

    const int h = blockIdx.x, n = blockIdx.y;
    const int tid = threadIdx.x, lane = tid & 31, warp = tid >> 5;
    const int wr = n >> 4, wc = n & 15;

    const unsigned qb = (unsigned)__cvta_generic_to_shared(sm.Qs);
    const unsigned kb = (unsigned)__cvta_generic_to_shared(sm.Ks);
    const unsigned vb = (unsigned)__cvta_generic_to_shared(sm.Vs);
    const unsigned bb = (unsigned)__cvta_generic_to_shared(sm.Bs);

    // QKV load: 2 threads per token
    {
        const int tok = tid & 127;
        const int l_t = (wr * 4 + (tok >> 5)) * W_IMG + wc * 32 + (tok & 31);
        const bf16* grow = qkv + (long)l_t * QKV_N + h * HD;
        if (tid < 128) {
            #pragma unroll
            for (int c = 0; c < 4; c++)
                cp16(qb + (tok * QS_STRIDE + c * 8) * 2, grow + c * 8);
            cp16(kb + (tok * QS_STRIDE + 0) * 2,  grow + 256);
            cp16(kb + (tok * QS_STRIDE + 8) * 2,  grow + 256 + 8);
        } else {
            cp16(kb + (tok * QS_STRIDE + 16) * 2, grow + 256 + 16);
            cp16(kb + (tok * QS_STRIDE + 24) * 2, grow + 256 + 24);
            #pragma unroll
            for (int c = 0; c < 4; c++)
                cp16(vb + (tok * QS_STRIDE + c * 8) * 2, grow + 512 + c * 8);
        }
        asm volatile("cp.async.commit_group;");
    }

    // bias tile load (overlaps QK mma)
    {
        const int row = tid >> 1, half = tid & 1;
        const bf16* brow = Bias + ((long)(h * NW + n) * T_WIN + row) * T_WIN + half * 64;
        #pragma unroll
        for (int c = 0; c < 8; c++)
            cp16(bb + (row * BS_STRIDE + half * 64 + c * 8) * 2, brow + c * 8);
        asm volatile("cp.async.commit_group;");
    }

    asm volatile("cp.async.wait_group 1;");
    __syncthreads();

    // S = Q @ K^T  (warp owns 16 query rows)
    const int mat = lane >> 3, r8 = lane & 7;
    float acc[16][4];
    #pragma unroll
    for (int j = 0; j < 16; j++)
        #pragma unroll
        for (int q = 0; q < 4; q++) acc[j][q] = 0.f;

    #pragma unroll
    for (int ks = 0; ks < 2; ks++) {
        unsigned a[4];
        ldsm4(a, qb + ((warp * 16 + (mat & 1) * 8 + r8) * QS_STRIDE
                       + (mat >> 1) * 8 + ks * 16) * 2);
        #pragma unroll
        for (int nt = 0; nt < 8; nt++) {
            unsigned bfr[4];
            ldsm4(bfr, kb + ((nt * 16 + (mat >> 1) * 8 + r8) * QS_STRIDE
                             + (mat & 1) * 8 + ks * 16) * 2);
            mma16816(acc[2 * nt + 0], a, &bfr[0]);
            mma16816(acc[2 * nt + 1], a, &bfr[2]);
        }
    }

    asm volatile("cp.async.wait_group 0;");
    __syncthreads();

    // bias add + softmax
    const int gr = lane >> 2, tig = lane & 3;
    float inv2[2];
    #pragma unroll
    for (int hf = 0; hf < 2; hf++) {
        const int row = warp * 16 + gr + hf * 8;
        float m = -1e30f;
        #pragma unroll
        for (int j = 0; j < 16; j++) {
            const __nv_bfloat162 bb2 = *reinterpret_cast<const __nv_bfloat162*>(
                &sm.Bs[row * BS_STRIDE + j * 8 + tig * 2]);
            const float2 bf = __bfloat1622float2(bb2);
            const float v0 = acc[j][hf * 2 + 0] + bf.x;
            const float v1 = acc[j][hf * 2 + 1] + bf.y;
            acc[j][hf * 2 + 0] = v0;
            acc[j][hf * 2 + 1] = v1;
            m = fmaxf(m, fmaxf(v0, v1));
        }
        m = fmaxf(m, __shfl_xor_sync(0xffffffffu, m, 1));
        m = fmaxf(m, __shfl_xor_sync(0xffffffffu, m, 2));
        float rs = 0.f;
        #pragma unroll
        for (int j = 0; j < 16; j++) {
            const float p0 = __expf(acc[j][hf * 2 + 0] - m);
            const float p1 = __expf(acc[j][hf * 2 + 1] - m);
            acc[j][hf * 2 + 0] = p0;
            acc[j][hf * 2 + 1] = p1;
            rs += p0 + p1;
        }
        rs += __shfl_xor_sync(0xffffffffu, rs, 1);
        rs += __shfl_xor_sync(0xffffffffu, rs, 2);
        inv2[hf] = 1.f / rs;
    }

    // O = P @ V
    float oacc[4][4];
    #pragma unroll
    for (int j = 0; j < 4; j++)
        #pragma unroll
        for (int q = 0; q < 4; q++) oacc[j][q] = 0.f;

    #pragma unroll
    for (int kk = 0; kk < 8; kk++) {
        unsigned ap[4];
        ap[0] = packbf(acc[2 * kk][0],     acc[2 * kk][1]);
        ap[1] = packbf(acc[2 * kk][2],     acc[2 * kk][3]);
        ap[2] = packbf(acc[2 * kk + 1][0], acc[2 * kk + 1][1]);
        ap[3] = packbf(acc[2 * kk + 1][2], acc[2 * kk + 1][3]);
        #pragma unroll
        for (int vt = 0; vt < 2; vt++) {
            unsigned bv4[4];
            ldsm4t(bv4, vb + ((kk * 16 + (mat & 1) * 8 + r8) * QS_STRIDE
                              + (mat >> 1) * 8 + vt * 16) * 2);
            mma16816(oacc[2 * vt + 0], ap, &bv4[0]);
            mma16816(oacc[2 * vt + 1], ap, &bv4[2]);
        }
    }

    // write O
    #pragma unroll
    for (int hf = 0; hf < 2; hf++) {
        const int row  = warp * 16 + gr + hf * 8;
        const int lrow = (wr * 4 + (row >> 5)) * W_IMG + wc * 32 + (row & 31);
        bf16* orow = O + (long)lrow * C_DIM + h * HD;
        const float sc = inv2[hf];
        #pragma unroll
        for (int j = 0; j < 4; j++) {
            *reinterpret_cast<__nv_bfloat162*>(orow + j * 8 + tig * 2) =
                __floats2bfloat162_rn(oacc[j][hf * 2 + 0] * sc,
                                      oacc[j][hf * 2 + 1] * sc);
        }
    }
}

// ---------------- launch ----------------
extern "C" void kernel_launch(void* const* d_in, const int* in_sizes, int n_in,
                              void* d_out, int out_size)
{
    const float* x      = (const float*)d_in[0];
    const float* pos    = (const float*)d_in[1];
    const float* n1g    = (const float*)d_in[2];
    const float* n1b    = (const float*)d_in[3];
    const float* wq     = (const float*)d_in[4];
    const float* bq     = (const float*)d_in[5];
    const float* wk     = (const float*)d_in[6];
    const float* bk     = (const float*)d_in[7];
    const float* wv     = (const float*)d_in[8];
    const float* bv     = (const float*)d_in[9];
    const float* wo     = (const float*)d_in[10];
    const float* bo     = (const float*)d_in[11];
    const float* n2g    = (const float*)d_in[12];
    const float* n2b    = (const float*)d_in[13];
    const float* wfc1   = (const float*)d_in[14];
    const float* bfc1   = (const float*)d_in[15];
    const float* wfc2   = (const float*)d_in[16];
    const float* bfc2   = (const float*)d_in[17];
    const float* pw1    = (const float*)d_in[18];
    const float* pb1    = (const float*)d_in[19];
    const float* bn_g   = (const float*)d_in[20];
    const float* bn_b   = (const float*)d_in[21];
    const float* bn_m   = (const float*)d_in[22];
    const float* bn_v   = (const float*)d_in[23];
    const float* pw2    = (const float*)d_in[24];
    const float* pb2    = (const float*)d_in[25];
    float* out = (float*)d_out;

    float* base = nullptr;
    cudaGetSymbolAddress((void**)&base, g_scratch);
    bf16*  xn   = (bf16*)(base + 0 * SZ_LC);
    bf16*  qkv  = (bf16*)(base + 1 * SZ_LC);     // slots 1-2
    bf16*  o    = (bf16*)(base + 3 * SZ_LC);
    float* x1   = base + 4 * SZ_LC;
    bf16*  xn2  = (bf16*)(base + 5 * SZ_LC);
    bf16*  hid  = (bf16*)(base + 6 * SZ_LC);     // slots 6-7
    bf16*  Bias = (bf16*)(base + 8 * SZ_LC);     // 64MB tail region

    bf16* wbf = nullptr;
    cudaGetSymbolAddress((void**)&wbf, g_wbf);
    bf16* wqkv_b = wbf + 0;
    bf16* wo_b   = wbf + 196608;
    bf16* wfc1_b = wbf + 262144;
    bf16* wfc2_b = wbf + 524288;
    float* bqkv = nullptr;
    cudaGetSymbolAddress((void**)&bqkv, g_bqkv);

    cudaFuncSetAttribute(mma_gemm<0, true>,  cudaFuncAttributeMaxDynamicSharedMemorySize, GEMM_SMEM);
    cudaFuncSetAttribute(mma_gemm<1, false>, cudaFuncAttributeMaxDynamicSharedMemorySize, GEMM_SMEM);
    cudaFuncSetAttribute(mma_gemm<2, true>,  cudaFuncAttributeMaxDynamicSharedMemorySize, GEMM_SMEM);
    cudaFuncSetAttribute(attn_kernel, cudaFuncAttributeMaxDynamicSharedMemorySize, (int)sizeof(AttnSmem));

    // 0. pack weights + positional bias tensor
    pack_kernel<<<768, 256>>>(wq, wk, wv, bq, bk, bv, wo, wfc1, wfc2);
    bias_kernel<<<NW, 256>>>(pos, pw1, pb1, bn_g, bn_b, bn_m, bn_v, pw2, pb2, Bias);

    // 1. xn = LN1(x)
    ln_kernel<<<L_TOK, 256>>>(x, n1g, n1b, xn);

    // 2. qkv = xn @ wqkv + bqkv   (q pre-scaled)
    mma_gemm<0, true><<<dim3(QKV_N / 128, L_TOK / 128), 256, GEMM_SMEM>>>(
        xn, wqkv_b, bqkv, nullptr, qkv, L_TOK, QKV_N, C_DIM, 1.f);

    // 3. attention
    attn_kernel<<<dim3(NH, NW), 256, sizeof(AttnSmem)>>>(qkv, Bias, o);

    // 4. x1 = x + o @ wo + bo
    mma_gemm<1, false><<<dim3(C_DIM / 128, L_TOK / 128), 256, GEMM_SMEM>>>(
        o, wo_b, bo, x, x1, L_TOK, C_DIM, C_DIM, 1.f);

    // 5. xn2 = LN2(x1)
    ln_kernel<<<L_TOK, 256>>>(x1, n2g, n2b, xn2);

    // 6. hid = gelu(xn2 @ wfc1 + bfc1)
    mma_gemm<2, true><<<dim3(HID_DIM / 128, L_TOK / 128), 256, GEMM_SMEM>>>(
        xn2, wfc1_b, bfc1, nullptr, hid, L_TOK, HID_DIM, C_DIM, 1.f);

    // 7. out = x1 + hid @ wfc2 + bfc2
    mma_gemm<1, false><<<dim3(C_DIM / 128, L_TOK / 128), 256, GEMM_SMEM>>>(
        hid, wfc2_b, bfc2, x1, out, L_TOK, C_DIM, HID_DIM, 1.f);
}